// round 3
// baseline (speedup 1.0000x reference)
#include <cuda_runtime.h>
#include <stdint.h>

// x [n,c,h,w] fp32; per (n,c) row of hw=4096 keep top-k by |x|.
// out = x (kept) or x*(1-tau) (dropped).
// One CTA per row. Exact k-th via MSD radix select on key = bits<<1
// (sign shifted out; unsigned order(key) == order(|x|)). Data in registers.
// Early-exit when the crossing radix class is kept whole.

constexpr int HW      = 4096;
constexpr int THREADS = 256;
constexpr int EPT     = HW / THREADS;   // 16
constexpr int NW      = THREADS / 32;   // 8
constexpr unsigned FULL = 0xFFFFFFFFu;

__global__ __launch_bounds__(THREADS)
void topk_blend_kernel(const float* __restrict__ x,
                       const float* __restrict__ tau_p,
                       const int*   __restrict__ k_p,
                       float*       __restrict__ out)
{
    __shared__ uint32_t hist[256][NW];     // [bin][copy] -> copy reduce vectorizes
    __shared__ uint32_t wsum[NW];
    __shared__ uint32_t wtie[NW];
    __shared__ uint32_t s_T, s_krem, s_done;

    const int tid  = threadIdx.x;
    const int wid  = tid >> 5;
    const int lane = tid & 31;
    const size_t base = (size_t)blockIdx.x * HW;

    // Blocked vectorized load of raw bits: thread t owns elements [t*16, t*16+16)
    uint32_t b[EPT];
    const uint4* __restrict__ xin = reinterpret_cast<const uint4*>(x + base);
    #pragma unroll
    for (int i = 0; i < EPT / 4; i++) {
        uint4 v = xin[tid * (EPT / 4) + i];
        b[i*4+0] = v.x; b[i*4+1] = v.y; b[i*4+2] = v.z; b[i*4+3] = v.w;
    }

    const float tau = __ldg(tau_p);
    const int   K   = __ldg(k_p);

    // zero histogram (2 x STS.128 per thread covers 2048 words)
    uint4* hv = reinterpret_cast<uint4*>(&hist[0][0]);
    hv[tid*2+0] = make_uint4(0,0,0,0);
    hv[tid*2+1] = make_uint4(0,0,0,0);
    __syncthreads();

    uint32_t T       = 0;      // key-space threshold
    int      t_need  = 0;      // #(key==T) to keep (exact mode)
    int      t_excl  = 0;      // this thread's exclusive tie rank
    bool     geq     = false;  // early-exit mode: keep = (key >= T)
    const bool sel   = (K > 0 && K < HW);

    if (sel) {
        uint32_t prefix = 0, krem = (uint32_t)K;
        uint32_t act = 0;      // active-element bitmask (valid from pass 2 on)
        int donepass = 4;

        for (int pass = 0; pass < 4; pass++) {
            const int shift = 24 - 8 * pass;

            // ---- histogram ----
            if (pass == 0) {
                // all elements; warp-aggregated atomics (digits concentrate)
                #pragma unroll
                for (int j = 0; j < EPT; j++) {
                    uint32_t dig = (b[j] << 1) >> 24;
                    unsigned m = __match_any_sync(FULL, dig);
                    if (lane == (int)__ffs(m) - 1)
                        atomicAdd(&hist[dig][wid], (uint32_t)__popc(m));
                }
            } else if (pass == 1) {
                // build active mask while histogramming
                uint32_t newm = 0;
                const uint32_t phi = prefix >> 24;
                #pragma unroll
                for (int j = 0; j < EPT; j++) {
                    uint32_t key = b[j] << 1;
                    if ((key >> 24) == phi) {
                        newm |= 1u << j;
                        atomicAdd(&hist[(key >> 16) & 0xFFu][wid], 1u);
                    }
                }
                act = newm;
            } else {
                // sparse: iterate only active bits
                uint32_t newm = 0, m = act;
                const uint32_t phi = prefix >> (shift + 8);
                while (m) {
                    int j = __ffs(m) - 1; m &= m - 1;
                    uint32_t key = b[j] << 1;
                    if ((key >> (shift + 8)) == phi) {
                        newm |= 1u << j;
                        atomicAdd(&hist[(key >> shift) & 0xFFu][wid], 1u);
                    }
                }
                act = newm;
            }
            __syncthreads();

            // ---- reduce copies for bin=tid, and zero them for the next pass
            // (each word is read by exactly one thread, so zeroing here is safe)
            uint4 h0 = reinterpret_cast<uint4*>(&hist[tid][0])[0];
            uint4 h1 = reinterpret_cast<uint4*>(&hist[tid][0])[1];
            reinterpret_cast<uint4*>(&hist[tid][0])[0] = make_uint4(0,0,0,0);
            reinterpret_cast<uint4*>(&hist[tid][0])[1] = make_uint4(0,0,0,0);
            uint32_t c = h0.x+h0.y+h0.z+h0.w + h1.x+h1.y+h1.z+h1.w;

            // ---- warp suffix scan over 32 bins, then cross-warp combine
            uint32_t s = c;
            #pragma unroll
            for (int off = 1; off < 32; off <<= 1) {
                uint32_t v = __shfl_down_sync(FULL, s, off);
                if (lane + off < 32) s += v;
            }
            if (lane == 0) wsum[wid] = s;
            __syncthreads();

            uint32_t hi = 0;
            #pragma unroll
            for (int w = 0; w < NW; w++) if (w > wid) hi += wsum[w];
            uint32_t incl  = s + hi;       // count of digits >= tid
            uint32_t above = incl - c;     // count of digits >  tid
            if (above < krem && krem <= incl) {     // exactly one thread
                uint32_t nk = krem - above;
                s_T    = prefix | ((uint32_t)tid << shift);
                s_krem = nk;
                s_done = (nk == c) ? 1u : 0u;       // whole class kept?
            }
            __syncthreads();
            prefix = s_T;
            krem   = s_krem;
            if (s_done) { donepass = pass; break; }
        }

        T = prefix;
        if (donepass < 4) {
            geq = true;                    // keep = key >= T, no ties
        } else {
            t_need = (int)krem;
            // Stable tie rank (lowest index first). Blocked layout => thread
            // order == index order. Rare path (~3% of rows).
            int myeq = 0;
            #pragma unroll
            for (int j = 0; j < EPT; j++) myeq += ((b[j] << 1) == T);
            uint32_t e = (uint32_t)myeq;
            #pragma unroll
            for (int off = 1; off < 32; off <<= 1) {
                uint32_t v = __shfl_up_sync(FULL, e, off);
                if (lane >= off) e += v;
            }
            if (lane == 31) wtie[wid] = e;
            __syncthreads();
            uint32_t lo = 0;
            #pragma unroll
            for (int w = 0; w < NW; w++) if (w < wid) lo += wtie[w];
            t_excl = (int)(e - (uint32_t)myeq + lo);
        }
    }

    // ---- apply: out = kept ? x : x*(1-tau)
    const float omt = 1.0f - tau;
    float4* __restrict__ yout = reinterpret_cast<float4*>(out + base);
    int rank = t_excl;
    #pragma unroll
    for (int i = 0; i < EPT / 4; i++) {
        float r[4];
        #pragma unroll
        for (int j = 0; j < 4; j++) {
            const int idx = i * 4 + j;
            uint32_t key = b[idx] << 1;
            bool keep;
            if (!sel)      keep = (K >= HW);
            else if (geq)  keep = (key >= T);
            else {
                keep = (key > T) | ((key == T) & (rank < t_need));
                rank += (key == T);
            }
            float xv = __uint_as_float(b[idx]);
            r[j] = keep ? xv : xv * omt;
        }
        yout[tid * (EPT / 4) + i] = make_float4(r[0], r[1], r[2], r[3]);
    }
}

extern "C" void kernel_launch(void* const* d_in, const int* in_sizes, int n_in,
                              void* d_out, int out_size)
{
    const float* x   = (const float*)d_in[0];
    const float* tau = (const float*)d_in[1];
    const int*   k   = (const int*)d_in[2];
    float*       out = (float*)d_out;
    const int    rows = in_sizes[0] / HW;   // n*c = 8192

    topk_blend_kernel<<<rows, THREADS>>>(x, tau, k, out);
}

// round 4
// speedup vs baseline: 1.0601x; 1.0601x over previous
#include <cuda_runtime.h>
#include <stdint.h>

// x [n,c,h,w] fp32; per (n,c) row of hw=4096 keep top-k by |x|.
// out = x (kept) or x*(1-tau) (dropped).
// One CTA per row. Exact k-th via MSD radix select on key = bits<<1.
// Data register-resident. whist[warp][bin] => bank = bin%32 (conflict-free).
// Early-exit when the crossing radix class is kept whole (common case).

constexpr int HW      = 4096;
constexpr int THREADS = 256;
constexpr int EPT     = HW / THREADS;   // 16
constexpr int NW      = THREADS / 32;   // 8
constexpr unsigned FULL = 0xFFFFFFFFu;

__global__ __launch_bounds__(THREADS)
void topk_blend_kernel(const float* __restrict__ x,
                       const float* __restrict__ tau_p,
                       const int*   __restrict__ k_p,
                       float*       __restrict__ out)
{
    __shared__ uint32_t whist[NW][256];   // [copy][bin]: atomic bank = bin%32
    __shared__ uint32_t wsum[NW];
    __shared__ uint32_t wtie[NW];
    __shared__ uint32_t s_T, s_krem, s_done;

    const int tid  = threadIdx.x;
    const int wid  = tid >> 5;
    const int lane = tid & 31;
    const size_t base = (size_t)blockIdx.x * HW;

    // Blocked vectorized load of raw bits: thread t owns elements [t*16, t*16+16)
    uint32_t b[EPT];
    const uint4* __restrict__ xin = reinterpret_cast<const uint4*>(x + base);
    #pragma unroll
    for (int i = 0; i < EPT / 4; i++) {
        uint4 v = xin[tid * (EPT / 4) + i];
        b[i*4+0] = v.x; b[i*4+1] = v.y; b[i*4+2] = v.z; b[i*4+3] = v.w;
    }

    const float tau = __ldg(tau_p);
    const int   K   = __ldg(k_p);

    // zero all copies once (thread tid owns bin tid across copies)
    #pragma unroll
    for (int w = 0; w < NW; w++) whist[w][tid] = 0;
    __syncthreads();

    uint32_t T      = 0;      // key-space threshold
    int      t_need = 0;      // #(key==T) to keep (exact mode)
    int      t_excl = 0;      // this thread's exclusive tie rank
    bool     geq    = false;  // early-exit mode: keep = (key >= T)
    const bool sel  = (K > 0 && K < HW);

    if (sel) {
        uint32_t prefix = 0, krem = (uint32_t)K;
        uint32_t act = 0;     // active-element bitmask (valid from pass 2 on)
        int donepass = 4;

        for (int pass = 0; pass < 4; pass++) {
            const int shift = 24 - 8 * pass;
            uint32_t* hist = whist[wid];

            // ---- histogram ----
            if (pass == 0) {
                // all elements; digits concentrate in few exponent bins ->
                // warp-aggregate via match_any
                #pragma unroll
                for (int j = 0; j < EPT; j++) {
                    uint32_t dig = (b[j] >> 23) & 0xFFu;   // key>>24
                    unsigned m = __match_any_sync(FULL, dig);
                    if (lane == (int)__ffs(m) - 1)
                        atomicAdd(&hist[dig], (uint32_t)__popc(m));
                }
            } else if (pass == 1) {
                // ~1/256 of elements active on average but clustered;
                // build active mask while histogramming (bins spread widely)
                uint32_t newm = 0;
                const uint32_t phi = prefix >> 24;
                #pragma unroll
                for (int j = 0; j < EPT; j++) {
                    uint32_t key = b[j] << 1;
                    if ((key >> 24) == phi) {
                        newm |= 1u << j;
                        atomicAdd(&hist[(key >> 16) & 0xFFu], 1u);
                    }
                }
                act = newm;
            } else {
                // sparse: iterate only active bits
                uint32_t newm = 0, m = act;
                const uint32_t phi = prefix >> (shift + 8);
                while (m) {
                    int j = __ffs(m) - 1; m &= m - 1;
                    uint32_t key = b[j] << 1;
                    if ((key >> (shift + 8)) == phi) {
                        newm |= 1u << j;
                        atomicAdd(&hist[(key >> shift) & 0xFFu], 1u);
                    }
                }
                act = newm;
            }
            __syncthreads();

            // ---- reduce copies for bin=tid; zero them for the next pass.
            // (bin-tid words are read only by thread tid, so zeroing here is
            // race-free without an extra barrier)
            uint32_t c = 0;
            #pragma unroll
            for (int w = 0; w < NW; w++) { c += whist[w][tid]; whist[w][tid] = 0; }

            // ---- warp suffix scan over 32 bins, then cross-warp combine
            uint32_t s = c;
            #pragma unroll
            for (int off = 1; off < 32; off <<= 1) {
                uint32_t v = __shfl_down_sync(FULL, s, off);
                if (lane + off < 32) s += v;
            }
            if (lane == 0) wsum[wid] = s;
            __syncthreads();

            uint32_t hi = 0;
            #pragma unroll
            for (int w = 0; w < NW; w++) if (w > wid) hi += wsum[w];
            uint32_t incl  = s + hi;       // count of digits >= tid
            uint32_t above = incl - c;     // count of digits >  tid
            if (above < krem && krem <= incl) {   // exactly one thread
                uint32_t nk = krem - above;
                s_T    = prefix | ((uint32_t)tid << shift);
                s_krem = nk;
                s_done = (nk == c) ? 1u : 0u;     // whole class kept?
            }
            __syncthreads();
            prefix = s_T;
            krem   = s_krem;
            if (s_done) { donepass = pass; break; }
        }

        T = prefix;
        if (donepass < 4) {
            geq = true;                    // keep = key >= T, no ties
        } else {
            t_need = (int)krem;
            // Stable tie rank (lowest index first). Blocked layout => thread
            // order == index order. Rare path.
            int myeq = 0;
            #pragma unroll
            for (int j = 0; j < EPT; j++) myeq += ((b[j] << 1) == T);
            uint32_t e = (uint32_t)myeq;
            #pragma unroll
            for (int off = 1; off < 32; off <<= 1) {
                uint32_t v = __shfl_up_sync(FULL, e, off);
                if (lane >= off) e += v;
            }
            if (lane == 31) wtie[wid] = e;
            __syncthreads();
            uint32_t lo = 0;
            #pragma unroll
            for (int w = 0; w < NW; w++) if (w < wid) lo += wtie[w];
            t_excl = (int)(e - (uint32_t)myeq + lo);
        }
    }

    // ---- apply: out = kept ? x : x*(1-tau)
    const float omt = 1.0f - tau;
    float4* __restrict__ yout = reinterpret_cast<float4*>(out + base);
    int rank = t_excl;
    #pragma unroll
    for (int i = 0; i < EPT / 4; i++) {
        float r[4];
        #pragma unroll
        for (int j = 0; j < 4; j++) {
            const int idx = i * 4 + j;
            uint32_t key = b[idx] << 1;
            bool keep;
            if (!sel)      keep = (K >= HW);
            else if (geq)  keep = (key >= T);
            else {
                keep = (key > T) | ((key == T) & (rank < t_need));
                rank += (key == T);
            }
            float xv = __uint_as_float(b[idx]);
            r[j] = keep ? xv : xv * omt;
        }
        yout[tid * (EPT / 4) + i] = make_float4(r[0], r[1], r[2], r[3]);
    }
}

extern "C" void kernel_launch(void* const* d_in, const int* in_sizes, int n_in,
                              void* d_out, int out_size)
{
    const float* x   = (const float*)d_in[0];
    const float* tau = (const float*)d_in[1];
    const int*   k   = (const int*)d_in[2];
    float*       out = (float*)d_out;
    const int    rows = in_sizes[0] / HW;   // n*c = 8192

    topk_blend_kernel<<<rows, THREADS>>>(x, tau, k, out);
}

// round 5
// speedup vs baseline: 1.1092x; 1.0463x over previous
#include <cuda_runtime.h>
#include <stdint.h>

// x [n,c,h,w] fp32; per (n,c) row of hw=4096 keep top-k by |x|.
// out = x (kept) or x*(1-tau) (dropped).
// One CTA per row. key = bits<<1 (unsigned order == |x| order).
// Pass 0 (8b) + pass 1 (8b) radix histograms, then gather the <=128
// candidates of the crossing 16-bit class and let ONE warp binary-search
// the remaining 16 bits via ballots. Radix passes 2-3 kept as fallback.

constexpr int HW      = 4096;
constexpr int THREADS = 256;
constexpr int EPT     = HW / THREADS;   // 16
constexpr int NW      = THREADS / 32;   // 8
constexpr int CAP     = 128;            // candidate list capacity
constexpr unsigned FULL = 0xFFFFFFFFu;

__global__ __launch_bounds__(THREADS)
void topk_blend_kernel(const float* __restrict__ x,
                       const float* __restrict__ tau_p,
                       const int*   __restrict__ k_p,
                       float*       __restrict__ out)
{
    __shared__ uint32_t whist[NW][256];   // [copy][bin] -> atomic bank = bin%32
    __shared__ uint32_t wsum[NW];
    __shared__ uint32_t wtie[NW];
    __shared__ uint32_t list[CAP];        // lower-16 bits of candidates
    __shared__ uint32_t s_T, s_krem;
    __shared__ uint32_t s_nlist;
    __shared__ uint32_t s_mode;           // 1 = geq (no ties), 0 = exact ties

    const int tid  = threadIdx.x;
    const int wid  = tid >> 5;
    const int lane = tid & 31;
    const size_t base = (size_t)blockIdx.x * HW;

    // Blocked vectorized load of raw bits: thread t owns elements [t*16, t*16+16)
    uint32_t b[EPT];
    const uint4* __restrict__ xin = reinterpret_cast<const uint4*>(x + base);
    #pragma unroll
    for (int i = 0; i < EPT / 4; i++) {
        uint4 v = xin[tid * (EPT / 4) + i];
        b[i*4+0] = v.x; b[i*4+1] = v.y; b[i*4+2] = v.z; b[i*4+3] = v.w;
    }

    const float tau = __ldg(tau_p);
    const int   K   = __ldg(k_p);

    // zero histogram copies (thread tid owns bin tid across copies)
    #pragma unroll
    for (int w = 0; w < NW; w++) whist[w][tid] = 0;
    __syncthreads();                                              // B1

    uint32_t T      = 0;
    int      t_need = 0;
    int      t_excl = 0;
    bool     geq    = false;
    const bool sel  = (K > 0 && K < HW);

    if (sel) {
        // ================= PASS 0 (key bits 31..24 = exp bits) ============
        {
            uint32_t* hist = whist[wid];
            #pragma unroll
            for (int j = 0; j < EPT; j++) {
                uint32_t dig = (b[j] >> 23) & 0xFFu;
                unsigned m = __match_any_sync(FULL, dig);
                if (lane == (int)__ffs(m) - 1)
                    atomicAdd(&hist[dig], (uint32_t)__popc(m));
            }
        }
        __syncthreads();                                          // B2

        uint32_t c = 0;
        #pragma unroll
        for (int w = 0; w < NW; w++) { c += whist[w][tid]; whist[w][tid] = 0; }
        uint32_t s = c;
        #pragma unroll
        for (int off = 1; off < 32; off <<= 1) {
            uint32_t v = __shfl_down_sync(FULL, s, off);
            if (lane + off < 32) s += v;
        }
        if (lane == 0) wsum[wid] = s;
        __syncthreads();                                          // B3
        {
            uint32_t hi = 0;
            #pragma unroll
            for (int w = 0; w < NW; w++) if (w > wid) hi += wsum[w];
            uint32_t incl = s + hi, above = incl - c;
            uint32_t krem0 = (uint32_t)K;
            if (above < krem0 && krem0 <= incl) {
                s_T    = (uint32_t)tid << 24;
                s_krem = krem0 - above;
            }
        }
        __syncthreads();                                          // B4
        uint32_t prefix = s_T;
        uint32_t krem   = s_krem;

        // ================= PASS 1 (key bits 23..16) =======================
        uint32_t act = 0;
        {
            uint32_t* hist = whist[wid];
            const uint32_t phi = prefix >> 24;
            #pragma unroll
            for (int j = 0; j < EPT; j++) {
                uint32_t key = b[j] << 1;
                if ((key >> 24) == phi) {
                    act |= 1u << j;
                    atomicAdd(&hist[(key >> 16) & 0xFFu], 1u);
                }
            }
        }
        __syncthreads();                                          // B5

        c = 0;
        #pragma unroll
        for (int w = 0; w < NW; w++) { c += whist[w][tid]; whist[w][tid] = 0; }
        s = c;
        #pragma unroll
        for (int off = 1; off < 32; off <<= 1) {
            uint32_t v = __shfl_down_sync(FULL, s, off);
            if (lane + off < 32) s += v;
        }
        if (lane == 0) wsum[wid] = s;
        if (tid == 0) s_nlist = 0;
        __syncthreads();                                          // B6
        {
            uint32_t hi = 0;
            #pragma unroll
            for (int w = 0; w < NW; w++) if (w > wid) hi += wsum[w];
            uint32_t incl = s + hi, above = incl - c;
            if (above < krem && krem <= incl) {
                s_T    = prefix | ((uint32_t)tid << 16);
                s_krem = krem - above;
            }
        }
        __syncthreads();                                          // B7
        prefix = s_T;          // top 16 key bits decided
        krem   = s_krem;

        // ================= GATHER crossing-class candidates ===============
        {
            uint32_t m = act;
            const uint32_t p16 = prefix >> 16;
            while (m) {
                int j = __ffs(m) - 1; m &= m - 1;
                uint32_t key = b[j] << 1;
                if ((key >> 16) == p16) {
                    uint32_t pos = atomicAdd(&s_nlist, 1u);
                    if (pos < CAP) list[pos] = key & 0xFFFFu;
                }
            }
        }
        __syncthreads();                                          // B8
        const uint32_t nlist = s_nlist;

        if (nlist <= CAP) {
            // ---- single-warp 16-bit binary search over candidates ----
            if (wid == 0) {
                const int nr = (int)((nlist + 31) >> 5);   // rounds (usually 1)
                uint32_t cand[4]; bool val[4];
                #pragma unroll
                for (int i = 0; i < 4; i++) {
                    int idx = lane + 32 * i;
                    val[i]  = (i < nr) && (idx < (int)nlist);
                    cand[i] = val[i] ? list[idx] : 0u;
                }
                auto cnt_ge = [&](uint32_t v) -> uint32_t {
                    uint32_t n = 0;
                    #pragma unroll
                    for (int i = 0; i < 4; i++)
                        n += (uint32_t)__popc(__ballot_sync(FULL, val[i] && cand[i] >= v));
                    return n;
                };
                uint32_t v = 0;
                #pragma unroll
                for (int bit = 15; bit >= 0; bit--) {
                    uint32_t t = v | (1u << bit);
                    if (cnt_ge(t) >= krem) v = t;
                }
                uint32_t n_gt = cnt_ge(v + 1);         // strictly greater
                uint32_t n_eq = cnt_ge(v) - n_gt;
                uint32_t need = krem - n_gt;           // >= 1
                if (lane == 0) {
                    s_T    = prefix | v;
                    s_krem = need;
                    s_mode = (need == n_eq) ? 1u : 0u;
                }
            }
            __syncthreads();                                      // B9
            T      = s_T;
            t_need = (int)s_krem;
            geq    = (s_mode != 0);
        } else {
            // ---- fallback: radix passes 2 & 3 (adversarial duplicates) ----
            #pragma unroll
            for (int pass = 2; pass < 4; pass++) {
                const int shift = 24 - 8 * pass;
                uint32_t* hist = whist[wid];
                uint32_t newm = 0, m = act;
                const uint32_t phi = prefix >> (shift + 8);
                while (m) {
                    int j = __ffs(m) - 1; m &= m - 1;
                    uint32_t key = b[j] << 1;
                    if ((key >> (shift + 8)) == phi) {
                        newm |= 1u << j;
                        atomicAdd(&hist[(key >> shift) & 0xFFu], 1u);
                    }
                }
                act = newm;
                __syncthreads();

                uint32_t cc = 0;
                #pragma unroll
                for (int w = 0; w < NW; w++) { cc += whist[w][tid]; whist[w][tid] = 0; }
                uint32_t ss = cc;
                #pragma unroll
                for (int off = 1; off < 32; off <<= 1) {
                    uint32_t vv = __shfl_down_sync(FULL, ss, off);
                    if (lane + off < 32) ss += vv;
                }
                if (lane == 0) wsum[wid] = ss;
                __syncthreads();
                uint32_t hi = 0;
                #pragma unroll
                for (int w = 0; w < NW; w++) if (w > wid) hi += wsum[w];
                uint32_t incl = ss + hi, above = incl - cc;
                if (above < krem && krem <= incl) {
                    s_T    = prefix | ((uint32_t)tid << shift);
                    s_krem = krem - above;
                }
                __syncthreads();
                prefix = s_T;
                krem   = s_krem;
            }
            T      = prefix;
            t_need = (int)krem;
            geq    = false;
        }

        // ---- stable tie rank (only when threshold value is duplicated) ----
        if (!geq) {
            int myeq = 0;
            #pragma unroll
            for (int j = 0; j < EPT; j++) myeq += ((b[j] << 1) == T);
            uint32_t e = (uint32_t)myeq;
            #pragma unroll
            for (int off = 1; off < 32; off <<= 1) {
                uint32_t v = __shfl_up_sync(FULL, e, off);
                if (lane >= off) e += v;
            }
            if (lane == 31) wtie[wid] = e;
            __syncthreads();
            uint32_t lo = 0;
            #pragma unroll
            for (int w = 0; w < NW; w++) if (w < wid) lo += wtie[w];
            t_excl = (int)(e - (uint32_t)myeq + lo);
        }
    }

    // ================= APPLY: out = kept ? x : x*(1-tau) ==================
    const float omt = 1.0f - tau;
    float4* __restrict__ yout = reinterpret_cast<float4*>(out + base);
    int rank = t_excl;
    #pragma unroll
    for (int i = 0; i < EPT / 4; i++) {
        float r[4];
        #pragma unroll
        for (int j = 0; j < 4; j++) {
            const int idx = i * 4 + j;
            uint32_t key = b[idx] << 1;
            bool keep;
            if (!sel)      keep = (K >= HW);
            else if (geq)  keep = (key >= T);
            else {
                keep = (key > T) | ((key == T) & (rank < t_need));
                rank += (key == T);
            }
            float xv = __uint_as_float(b[idx]);
            r[j] = keep ? xv : xv * omt;
        }
        yout[tid * (EPT / 4) + i] = make_float4(r[0], r[1], r[2], r[3]);
    }
}

extern "C" void kernel_launch(void* const* d_in, const int* in_sizes, int n_in,
                              void* d_out, int out_size)
{
    const float* x   = (const float*)d_in[0];
    const float* tau = (const float*)d_in[1];
    const int*   k   = (const int*)d_in[2];
    float*       out = (float*)d_out;
    const int    rows = in_sizes[0] / HW;   // n*c = 8192

    topk_blend_kernel<<<rows, THREADS>>>(x, tau, k, out);
}

// round 6
// speedup vs baseline: 1.1123x; 1.0028x over previous
#include <cuda_runtime.h>
#include <stdint.h>

// x [n,c,h,w] fp32; per (n,c) row of hw=4096 keep top-k by |x|.
// out = x (kept) or x*(1-tau) (dropped).
// One CTA (512 thr) per row. key = bits<<1. Radix pass0+pass1 (8b each),
// then gather <=128 candidates of the crossing 16-bit class; one warp
// ballot-binary-searches the low 16 bits. Radix passes 2-3 as fallback.

constexpr int HW      = 4096;
constexpr int THREADS = 512;
constexpr int EPT     = HW / THREADS;   // 8
constexpr int NW      = THREADS / 32;   // 16 warps
constexpr int NH      = 8;              // histogram copies (warp pairs share)
constexpr int CAP     = 128;
constexpr unsigned FULL = 0xFFFFFFFFu;

__global__ __launch_bounds__(THREADS)
void topk_blend_kernel(const float* __restrict__ x,
                       const float* __restrict__ tau_p,
                       const int*   __restrict__ k_p,
                       float*       __restrict__ out)
{
    __shared__ uint32_t whist[NH][256];   // [copy][bin] -> atomic bank = bin%32
    __shared__ uint32_t wsum[NH];         // 8 scan warps
    __shared__ uint32_t wtie[NW];
    __shared__ uint32_t list[CAP];
    __shared__ uint32_t s_T, s_krem;
    __shared__ uint32_t s_nlist;
    __shared__ uint32_t s_mode;

    const int tid  = threadIdx.x;
    const int wid  = tid >> 5;
    const int lane = tid & 31;
    const size_t base = (size_t)blockIdx.x * HW;

    // Blocked load: thread t owns elements [t*8, t*8+8)
    uint32_t b[EPT];
    const uint4* __restrict__ xin = reinterpret_cast<const uint4*>(x + base);
    #pragma unroll
    for (int i = 0; i < EPT / 4; i++) {
        uint4 v = xin[tid * (EPT / 4) + i];
        b[i*4+0] = v.x; b[i*4+1] = v.y; b[i*4+2] = v.z; b[i*4+3] = v.w;
    }

    const float tau = __ldg(tau_p);
    const int   K   = __ldg(k_p);

    // zero histograms: 2048 words / 512 threads = 1 uint4 per thread
    reinterpret_cast<uint4*>(&whist[0][0])[tid] = make_uint4(0,0,0,0);
    __syncthreads();                                              // B1

    uint32_t T      = 0;
    int      t_need = 0;
    int      t_excl = 0;
    bool     geq    = false;
    const bool sel  = (K > 0 && K < HW);

    if (sel) {
        uint32_t* hist = whist[wid >> 1];

        // ================ PASS 0 (key bits 31..24) ================
        #pragma unroll
        for (int j = 0; j < EPT; j++) {
            uint32_t dig = (b[j] >> 23) & 0xFFu;
            unsigned m = __match_any_sync(FULL, dig);
            if (lane == (int)__ffs(m) - 1)
                atomicAdd(&hist[dig], (uint32_t)__popc(m));
        }
        __syncthreads();                                          // B2

        // reduce copies + suffix scan (first 256 threads)
        uint32_t s = 0, c = 0;
        if (tid < 256) {
            #pragma unroll
            for (int w = 0; w < NH; w++) { c += whist[w][tid]; whist[w][tid] = 0; }
            s = c;
            #pragma unroll
            for (int off = 1; off < 32; off <<= 1) {
                uint32_t v = __shfl_down_sync(FULL, s, off);
                if (lane + off < 32) s += v;
            }
            if (lane == 0) wsum[wid] = s;
        }
        __syncthreads();                                          // B3
        if (tid < 256) {
            uint32_t hi = 0;
            #pragma unroll
            for (int w = 0; w < NH; w++) if (w > wid) hi += wsum[w];
            uint32_t incl = s + hi, above = incl - c;
            uint32_t krem0 = (uint32_t)K;
            if (above < krem0 && krem0 <= incl) {
                s_T    = (uint32_t)tid << 24;
                s_krem = krem0 - above;
            }
        }
        __syncthreads();                                          // B4
        uint32_t prefix = s_T;
        uint32_t krem   = s_krem;

        // ================ PASS 1 (key bits 23..16) ================
        uint32_t act = 0;
        {
            const uint32_t phi = prefix >> 24;
            #pragma unroll
            for (int j = 0; j < EPT; j++) {
                uint32_t key = b[j] << 1;
                if ((key >> 24) == phi) {
                    act |= 1u << j;
                    atomicAdd(&hist[(key >> 16) & 0xFFu], 1u);
                }
            }
        }
        __syncthreads();                                          // B5

        s = 0; c = 0;
        if (tid < 256) {
            #pragma unroll
            for (int w = 0; w < NH; w++) { c += whist[w][tid]; whist[w][tid] = 0; }
            s = c;
            #pragma unroll
            for (int off = 1; off < 32; off <<= 1) {
                uint32_t v = __shfl_down_sync(FULL, s, off);
                if (lane + off < 32) s += v;
            }
            if (lane == 0) wsum[wid] = s;
        }
        if (tid == 0) s_nlist = 0;
        __syncthreads();                                          // B6
        if (tid < 256) {
            uint32_t hi = 0;
            #pragma unroll
            for (int w = 0; w < NH; w++) if (w > wid) hi += wsum[w];
            uint32_t incl = s + hi, above = incl - c;
            if (above < krem && krem <= incl) {
                s_T    = prefix | ((uint32_t)tid << 16);
                s_krem = krem - above;
            }
        }
        __syncthreads();                                          // B7
        prefix = s_T;
        krem   = s_krem;

        // ================ GATHER candidates =======================
        {
            uint32_t m = act;
            const uint32_t p16 = prefix >> 16;
            while (m) {
                int j = __ffs(m) - 1; m &= m - 1;
                uint32_t key = b[j] << 1;
                if ((key >> 16) == p16) {
                    uint32_t pos = atomicAdd(&s_nlist, 1u);
                    if (pos < CAP) list[pos] = key & 0xFFFFu;
                }
            }
        }
        __syncthreads();                                          // B8
        const uint32_t nlist = s_nlist;

        if (nlist <= CAP) {
            // ---- single-warp ballot binary search on low 16 bits ----
            if (wid == 0) {
                const int nr = (int)((nlist + 31) >> 5);
                uint32_t cand[4]; bool val[4];
                #pragma unroll
                for (int i = 0; i < 4; i++) {
                    int idx = lane + 32 * i;
                    val[i]  = (i < nr) && (idx < (int)nlist);
                    cand[i] = val[i] ? list[idx] : 0u;
                }
                auto cnt_ge = [&](uint32_t v) -> uint32_t {
                    uint32_t n = 0;
                    #pragma unroll
                    for (int i = 0; i < 4; i++)
                        n += (uint32_t)__popc(__ballot_sync(FULL, val[i] && cand[i] >= v));
                    return n;
                };
                uint32_t v = 0;
                #pragma unroll
                for (int bit = 15; bit >= 0; bit--) {
                    uint32_t t = v | (1u << bit);
                    if (cnt_ge(t) >= krem) v = t;
                }
                uint32_t n_gt = cnt_ge(v + 1);
                uint32_t n_eq = cnt_ge(v) - n_gt;
                uint32_t need = krem - n_gt;
                if (lane == 0) {
                    s_T    = prefix | v;
                    s_krem = need;
                    s_mode = (need == n_eq) ? 1u : 0u;
                }
            }
            __syncthreads();                                      // B9
            T      = s_T;
            t_need = (int)s_krem;
            geq    = (s_mode != 0);
        } else {
            // ---- fallback: radix passes 2 & 3 ----
            #pragma unroll
            for (int pass = 2; pass < 4; pass++) {
                const int shift = 24 - 8 * pass;
                uint32_t newm = 0, m = act;
                const uint32_t phi = prefix >> (shift + 8);
                while (m) {
                    int j = __ffs(m) - 1; m &= m - 1;
                    uint32_t key = b[j] << 1;
                    if ((key >> (shift + 8)) == phi) {
                        newm |= 1u << j;
                        atomicAdd(&hist[(key >> shift) & 0xFFu], 1u);
                    }
                }
                act = newm;
                __syncthreads();

                uint32_t ss = 0, cc = 0;
                if (tid < 256) {
                    #pragma unroll
                    for (int w = 0; w < NH; w++) { cc += whist[w][tid]; whist[w][tid] = 0; }
                    ss = cc;
                    #pragma unroll
                    for (int off = 1; off < 32; off <<= 1) {
                        uint32_t vv = __shfl_down_sync(FULL, ss, off);
                        if (lane + off < 32) ss += vv;
                    }
                    if (lane == 0) wsum[wid] = ss;
                }
                __syncthreads();
                if (tid < 256) {
                    uint32_t hi = 0;
                    #pragma unroll
                    for (int w = 0; w < NH; w++) if (w > wid) hi += wsum[w];
                    uint32_t incl = ss + hi, above = incl - cc;
                    if (above < krem && krem <= incl) {
                        s_T    = prefix | ((uint32_t)tid << shift);
                        s_krem = krem - above;
                    }
                }
                __syncthreads();
                prefix = s_T;
                krem   = s_krem;
            }
            T      = prefix;
            t_need = (int)krem;
            geq    = false;
        }

        // ---- stable tie rank (rare: duplicated threshold value) ----
        if (!geq) {
            int myeq = 0;
            #pragma unroll
            for (int j = 0; j < EPT; j++) myeq += ((b[j] << 1) == T);
            uint32_t e = (uint32_t)myeq;
            #pragma unroll
            for (int off = 1; off < 32; off <<= 1) {
                uint32_t v = __shfl_up_sync(FULL, e, off);
                if (lane >= off) e += v;
            }
            if (lane == 31) wtie[wid] = e;
            __syncthreads();
            uint32_t lo = 0;
            #pragma unroll
            for (int w = 0; w < NW; w++) if (w < wid) lo += wtie[w];
            t_excl = (int)(e - (uint32_t)myeq + lo);
        }
    }

    // ================ APPLY: out = kept ? x : x*(1-tau) ================
    const float omt = 1.0f - tau;
    float4* __restrict__ yout = reinterpret_cast<float4*>(out + base);
    int rank = t_excl;
    #pragma unroll
    for (int i = 0; i < EPT / 4; i++) {
        float r[4];
        #pragma unroll
        for (int j = 0; j < 4; j++) {
            const int idx = i * 4 + j;
            uint32_t key = b[idx] << 1;
            bool keep;
            if (!sel)      keep = (K >= HW);
            else if (geq)  keep = (key >= T);
            else {
                keep = (key > T) | ((key == T) & (rank < t_need));
                rank += (key == T);
            }
            float xv = __uint_as_float(b[idx]);
            r[j] = keep ? xv : xv * omt;
        }
        yout[tid * (EPT / 4) + i] = make_float4(r[0], r[1], r[2], r[3]);
    }
}

extern "C" void kernel_launch(void* const* d_in, const int* in_sizes, int n_in,
                              void* d_out, int out_size)
{
    const float* x   = (const float*)d_in[0];
    const float* tau = (const float*)d_in[1];
    const int*   k   = (const int*)d_in[2];
    float*       out = (float*)d_out;
    const int    rows = in_sizes[0] / HW;   // n*c = 8192

    topk_blend_kernel<<<rows, THREADS>>>(x, tau, k, out);
}